// round 2
// baseline (speedup 1.0000x reference)
#include <cuda_runtime.h>
#include <cstdint>

// Segment mean readout:
//   in0: atom_hiddens  float32 [N_ATOMS=1000000, D=300]
//   in1: a_scope       int32   [N_GRAPHS=50000, 2]  (start, size) contiguous segments
//        (numpy int64 in the reference, but JAX x64-disabled downcasts to int32)
//   out: mol_vecs      float32 [N_GRAPHS, 300]
//
// D = 300 floats = 75 float4 per row; row stride 1200 B (16B aligned).
// One warp per graph: lane l covers float4 columns l, l+32, l+64 (l+64 < 75 iff l < 11).

#define VEC_PER_ROW 75

__global__ void readout_mean_kernel(const float4* __restrict__ x,
                                    const int* __restrict__ scope,
                                    float4* __restrict__ out,
                                    int n_graphs) {
    const int gwarp = (blockIdx.x * blockDim.x + threadIdx.x) >> 5;
    const int lane  = threadIdx.x & 31;
    if (gwarp >= n_graphs) return;

    const int start = scope[2 * gwarp];
    const int size  = scope[2 * gwarp + 1];

    float4 a0 = make_float4(0.f, 0.f, 0.f, 0.f);
    float4 a1 = make_float4(0.f, 0.f, 0.f, 0.f);
    float4 a2 = make_float4(0.f, 0.f, 0.f, 0.f);

    const float4* __restrict__ row = x + (long long)start * VEC_PER_ROW;
    const bool has3 = (lane < VEC_PER_ROW - 64);  // lane < 11

    int r = 0;
    // 2x software pipelined unroll: 6 independent loads in flight before any FADD retires.
    for (; r + 2 <= size; r += 2) {
        const float4* p0 = row + (long long)r * VEC_PER_ROW;
        const float4* p1 = p0 + VEC_PER_ROW;
        float4 v00 = p0[lane];
        float4 v01 = p0[lane + 32];
        float4 v10 = p1[lane];
        float4 v11 = p1[lane + 32];
        float4 v02, v12;
        if (has3) { v02 = p0[lane + 64]; v12 = p1[lane + 64]; }
        a0.x += v00.x; a0.y += v00.y; a0.z += v00.z; a0.w += v00.w;
        a1.x += v01.x; a1.y += v01.y; a1.z += v01.z; a1.w += v01.w;
        a0.x += v10.x; a0.y += v10.y; a0.z += v10.z; a0.w += v10.w;
        a1.x += v11.x; a1.y += v11.y; a1.z += v11.z; a1.w += v11.w;
        if (has3) {
            a2.x += v02.x; a2.y += v02.y; a2.z += v02.z; a2.w += v02.w;
            a2.x += v12.x; a2.y += v12.y; a2.z += v12.z; a2.w += v12.w;
        }
    }
    for (; r < size; ++r) {
        const float4* p = row + (long long)r * VEC_PER_ROW;
        float4 v0 = p[lane];
        float4 v1 = p[lane + 32];
        a0.x += v0.x; a0.y += v0.y; a0.z += v0.z; a0.w += v0.w;
        a1.x += v1.x; a1.y += v1.y; a1.z += v1.z; a1.w += v1.w;
        if (has3) {
            float4 v2 = p[lane + 64];
            a2.x += v2.x; a2.y += v2.y; a2.z += v2.z; a2.w += v2.w;
        }
    }

    // denom = max(size,1); size==0 -> acc is 0 and we write zeros (matches jnp.where).
    const float inv = (size > 0) ? (1.0f / (float)size) : 0.0f;

    float4* o = out + (long long)gwarp * VEC_PER_ROW;
    float4 w0 = make_float4(a0.x * inv, a0.y * inv, a0.z * inv, a0.w * inv);
    float4 w1 = make_float4(a1.x * inv, a1.y * inv, a1.z * inv, a1.w * inv);
    o[lane]      = w0;
    o[lane + 32] = w1;
    if (has3) {
        float4 w2 = make_float4(a2.x * inv, a2.y * inv, a2.z * inv, a2.w * inv);
        o[lane + 64] = w2;
    }
}

extern "C" void kernel_launch(void* const* d_in, const int* in_sizes, int n_in,
                              void* d_out, int out_size) {
    const float4* x = (const float4*)d_in[0];      // atom_hiddens, float32 [1e6, 300]
    const int* scope = (const int*)d_in[1];        // a_scope, int32 [50000, 2]
    float4* out = (float4*)d_out;

    const int n_graphs = in_sizes[1] / 2;          // 100000 ints -> 50000 graphs
    const int threads = 256;                       // 8 warps/block
    const int blocks = (n_graphs * 32 + threads - 1) / threads;

    readout_mean_kernel<<<blocks, threads>>>(x, scope, out, n_graphs);
}

// round 3
// speedup vs baseline: 1.0424x; 1.0424x over previous
#include <cuda_runtime.h>
#include <cstdint>

// Segment mean readout (HBM-bound stream):
//   in0: atom_hiddens  float32 [1e6, 300]
//   in1: a_scope       int32   [50000, 2] (start, size), contiguous segments
//   out: mol_vecs      float32 [50000, 300]
//
// One warp per graph. Row = 75 float4 (1200 B). Lane l covers float4 cols
// l, l+32, and l+64 (predicated l<11). Streaming (.cs) loads/stores: one-pass
// data, evict-first to keep L2 from thrashing on the 1.2 GB read stream.

#define VEC_PER_ROW 75

__global__ void __launch_bounds__(256)
readout_mean_kernel(const float4* __restrict__ x,
                    const int* __restrict__ scope,
                    float4* __restrict__ out,
                    int n_graphs) {
    const int gwarp = (blockIdx.x * blockDim.x + threadIdx.x) >> 5;
    const int lane  = threadIdx.x & 31;
    if (gwarp >= n_graphs) return;

    const int start = scope[2 * gwarp];
    const int size  = scope[2 * gwarp + 1];

    float4 a0 = make_float4(0.f, 0.f, 0.f, 0.f);
    float4 a1 = make_float4(0.f, 0.f, 0.f, 0.f);
    float4 a2 = make_float4(0.f, 0.f, 0.f, 0.f);

    const bool has3 = (lane < VEC_PER_ROW - 64);  // lane < 11

    // Per-lane base pointer; step by whole rows (no per-iter IMAD chains).
    const float4* p = x + (long long)start * VEC_PER_ROW + lane;

    int r = 0;
    // 2x software pipeline: up to 6 independent streaming loads in flight.
    for (; r + 2 <= size; r += 2, p += 2 * VEC_PER_ROW) {
        float4 v00 = __ldcs(p);
        float4 v01 = __ldcs(p + 32);
        float4 v10 = __ldcs(p + VEC_PER_ROW);
        float4 v11 = __ldcs(p + VEC_PER_ROW + 32);
        float4 v02, v12;
        if (has3) {
            v02 = __ldcs(p + 64);
            v12 = __ldcs(p + VEC_PER_ROW + 64);
        }
        a0.x += v00.x; a0.y += v00.y; a0.z += v00.z; a0.w += v00.w;
        a1.x += v01.x; a1.y += v01.y; a1.z += v01.z; a1.w += v01.w;
        a0.x += v10.x; a0.y += v10.y; a0.z += v10.z; a0.w += v10.w;
        a1.x += v11.x; a1.y += v11.y; a1.z += v11.z; a1.w += v11.w;
        if (has3) {
            a2.x += v02.x; a2.y += v02.y; a2.z += v02.z; a2.w += v02.w;
            a2.x += v12.x; a2.y += v12.y; a2.z += v12.z; a2.w += v12.w;
        }
    }
    for (; r < size; ++r, p += VEC_PER_ROW) {
        float4 v0 = __ldcs(p);
        float4 v1 = __ldcs(p + 32);
        a0.x += v0.x; a0.y += v0.y; a0.z += v0.z; a0.w += v0.w;
        a1.x += v1.x; a1.y += v1.y; a1.z += v1.z; a1.w += v1.w;
        if (has3) {
            float4 v2 = __ldcs(p + 64);
            a2.x += v2.x; a2.y += v2.y; a2.z += v2.z; a2.w += v2.w;
        }
    }

    // denom = max(size,1); size==0 -> zeros (matches reference's where()).
    const float inv = (size > 0) ? (1.0f / (float)size) : 0.0f;

    float4* o = out + (long long)gwarp * VEC_PER_ROW + lane;
    __stcs(o,      make_float4(a0.x * inv, a0.y * inv, a0.z * inv, a0.w * inv));
    __stcs(o + 32, make_float4(a1.x * inv, a1.y * inv, a1.z * inv, a1.w * inv));
    if (has3) {
        __stcs(o + 64, make_float4(a2.x * inv, a2.y * inv, a2.z * inv, a2.w * inv));
    }
}

extern "C" void kernel_launch(void* const* d_in, const int* in_sizes, int n_in,
                              void* d_out, int out_size) {
    const float4* x = (const float4*)d_in[0];   // atom_hiddens f32 [1e6,300]
    const int* scope = (const int*)d_in[1];     // a_scope int32 [50000,2]
    float4* out = (float4*)d_out;

    const int n_graphs = in_sizes[1] / 2;       // 100000 ints -> 50000 graphs
    const int threads = 256;                    // 8 warps/block
    const int blocks = (n_graphs * 32 + threads - 1) / threads;

    readout_mean_kernel<<<blocks, threads>>>(x, scope, out, n_graphs);
}